// round 6
// baseline (speedup 1.0000x reference)
#include <cuda_runtime.h>

// KGAT neighbor attention, algebraically folded.
//
// Identity 1: no activation between fc1 and fc2 ->
//   logits = concat @ (W1 @ W2) + const.  v = W1@W2 = [v1|v2|v3].
// Identity 2: softmax over k is shift-invariant, and e.v1 + c is constant
//   over k -> attention weights depend ONLY on ne_k.v2 + nr_k.v3.
// So: att = softmax_k(ne_k.v2 + nr_k.v3), out = [e, sum_k att_k * ne_k].
//
// Kernel 1: warp-per-output fold of v2,v3 (coalesced, one wave).
// Kernel 2: streaming warp-per-pair, evict-first, 5 blocks/SM.

#define D        128
#define K        5
#define WARPS_PER_BLOCK 8
#define THREADS  (WARPS_PER_BLOCK * 32)

__device__ __align__(16) float g_v[256];   // v2 (128) | v3 (128)

__device__ __forceinline__ float warp_sum(float x) {
    #pragma unroll
    for (int o = 16; o > 0; o >>= 1)
        x += __shfl_xor_sync(0xffffffffu, x, o);
    return x;
}

__device__ __forceinline__ float dot4(float4 a, float4 b) {
    return fmaf(a.x, b.x, fmaf(a.y, b.y, fmaf(a.z, b.z, a.w * b.w)));
}

// One warp per output element f (0..255): folds rows 128..383 of W1 with W2.
// (Rows 0..127 = v1 are unused: softmax is invariant to the e.v1 + c shift.)
__global__ void __launch_bounds__(THREADS)
fold_mlp_kernel(const float* __restrict__ W1,   // [384, 128] row-major
                const float* __restrict__ W2)   // [128, 1]
{
    const int warp = (blockIdx.x * blockDim.x + threadIdx.x) >> 5;
    const int lane = threadIdx.x & 31;
    if (warp >= 256) return;

    const float4 w2 = __ldg(reinterpret_cast<const float4*>(W2) + lane);
    const float4 a  = __ldg(reinterpret_cast<const float4*>(W1 + (size_t)(warp + 128) * 128) + lane);
    const float s = warp_sum(dot4(a, w2));
    if (lane == 0) g_v[warp] = s;
}

__global__ void __launch_bounds__(THREADS, 5)
kgat_kernel(const float* __restrict__ ent,     // [P, 128]
            const float* __restrict__ ne,      // [P, K, 128]
            const float* __restrict__ nr,      // [P, K, 128]
            float* __restrict__ out,           // [P, 256]
            int total_pairs)
{
    const int warp = (blockIdx.x * blockDim.x + threadIdx.x) >> 5;
    const int lane = threadIdx.x & 31;
    if (warp >= total_pairs) return;

    // Folded weight vectors (heavily reused -> default caching)
    const float4* vp = reinterpret_cast<const float4*>(g_v);
    const float4 v2 = __ldg(vp + lane);        // v[128:256] of original
    const float4 v3 = __ldg(vp + 32 + lane);   // v[256:384]

    // Streaming data: zero reuse -> evict-first (.cs)
    const float4* ep  = reinterpret_cast<const float4*>(ent + (size_t)warp * D);
    const float4* nep = reinterpret_cast<const float4*>(ne + (size_t)warp * (K * D));
    const float4* nrp = reinterpret_cast<const float4*>(nr + (size_t)warp * (K * D));
    float4* op = reinterpret_cast<float4*>(out + (size_t)warp * (2 * D));

    // Entity passthrough: load + store immediately (independent of softmax)
    const float4 e4 = __ldcs(ep + lane);
    __stcs(op + lane, e4);

    float4 nek[K];
    float  logit[K];
    #pragma unroll
    for (int k = 0; k < K; k++) {
        nek[k]          = __ldcs(nep + k * 32 + lane);
        const float4 r4 = __ldcs(nrp + k * 32 + lane);
        logit[k] = dot4(nek[k], v2) + dot4(r4, v3);
    }
    #pragma unroll
    for (int k = 0; k < K; k++)
        logit[k] = warp_sum(logit[k]);   // every lane has all K logits

    // Softmax over K=5 (fp32)
    float m = logit[0];
    #pragma unroll
    for (int k = 1; k < K; k++) m = fmaxf(m, logit[k]);
    float ex[K], sum = 0.0f;
    #pragma unroll
    for (int k = 0; k < K; k++) { ex[k] = __expf(logit[k] - m); sum += ex[k]; }
    const float inv = 1.0f / sum;

    // Weighted sum of neighbor entity embeddings
    float4 acc = make_float4(0.f, 0.f, 0.f, 0.f);
    #pragma unroll
    for (int k = 0; k < K; k++) {
        const float a = ex[k] * inv;
        acc.x = fmaf(a, nek[k].x, acc.x);
        acc.y = fmaf(a, nek[k].y, acc.y);
        acc.z = fmaf(a, nek[k].z, acc.z);
        acc.w = fmaf(a, nek[k].w, acc.w);
    }

    __stcs(op + 32 + lane, acc);
}

extern "C" void kernel_launch(void* const* d_in, const int* in_sizes, int n_in,
                              void* d_out, int out_size) {
    const float* ent = (const float*)d_in[0];   // entity_embedding   [B,N,128]
    const float* ne  = (const float*)d_in[1];   // neigh_entity       [B,N,5,128]
    const float* nr  = (const float*)d_in[2];   // neigh_relation     [B,N,5,128]
    const float* W1  = (const float*)d_in[3];   // [384,128]
    const float* W2  = (const float*)d_in[5];   // [128,1]
    float* out = (float*)d_out;

    const int total_pairs = in_sizes[0] / D;    // B*N

    // 256 warps needed -> 32 blocks of 8 warps
    fold_mlp_kernel<<<32, THREADS>>>(W1, W2);

    const int blocks = (total_pairs + WARPS_PER_BLOCK - 1) / WARPS_PER_BLOCK;
    kgat_kernel<<<blocks, THREADS>>>(ent, ne, nr, out, total_pairs);
}

// round 7
// speedup vs baseline: 1.0573x; 1.0573x over previous
#include <cuda_runtime.h>

// KGAT neighbor attention, algebraically folded.
//
// Identity 1: no activation between fc1 and fc2 ->
//   logits = concat @ (W1 @ W2) + const.  v = W1@W2 = [v1|v2|v3].
// Identity 2: softmax over k is shift-invariant, and e.v1 + c is constant
//   over k -> attention weights depend ONLY on ne_k.v2 + nr_k.v3.
// So: att = softmax_k(ne_k.v2 + nr_k.v3), out = [e, sum_k att_k * ne_k].
//
// Kernel 1: warp-per-output fold of v2,v3 (coalesced, one wave).
// Kernel 2: streaming warp-per-pair. All 11 LDG.128 front-batched (stores
// deferred to the end: an early dependent store would block the load burst),
// evict-first policy, 5 blocks/SM.

#define D        128
#define K        5
#define WARPS_PER_BLOCK 8
#define THREADS  (WARPS_PER_BLOCK * 32)

__device__ __align__(16) float g_v[256];   // v2 (128) | v3 (128)

__device__ __forceinline__ float warp_sum(float x) {
    #pragma unroll
    for (int o = 16; o > 0; o >>= 1)
        x += __shfl_xor_sync(0xffffffffu, x, o);
    return x;
}

__device__ __forceinline__ float dot4(float4 a, float4 b) {
    return fmaf(a.x, b.x, fmaf(a.y, b.y, fmaf(a.z, b.z, a.w * b.w)));
}

// One warp per output element f (0..255): folds rows 128..383 of W1 with W2.
// (Rows 0..127 = v1 are unused: softmax is invariant to the e.v1 + c shift.)
__global__ void __launch_bounds__(THREADS)
fold_mlp_kernel(const float* __restrict__ W1,   // [384, 128] row-major
                const float* __restrict__ W2)   // [128, 1]
{
    const int warp = (blockIdx.x * blockDim.x + threadIdx.x) >> 5;
    const int lane = threadIdx.x & 31;
    if (warp >= 256) return;

    const float4 w2 = __ldg(reinterpret_cast<const float4*>(W2) + lane);
    const float4 a  = __ldg(reinterpret_cast<const float4*>(W1 + (size_t)(warp + 128) * 128) + lane);
    const float s = warp_sum(dot4(a, w2));
    if (lane == 0) g_v[warp] = s;
}

__global__ void __launch_bounds__(THREADS, 5)
kgat_kernel(const float* __restrict__ ent,     // [P, 128]
            const float* __restrict__ ne,      // [P, K, 128]
            const float* __restrict__ nr,      // [P, K, 128]
            float* __restrict__ out,           // [P, 256]
            int total_pairs)
{
    const int warp = (blockIdx.x * blockDim.x + threadIdx.x) >> 5;
    const int lane = threadIdx.x & 31;
    if (warp >= total_pairs) return;

    // Folded weight vectors (heavily reused -> default caching)
    const float4* vp = reinterpret_cast<const float4*>(g_v);
    const float4 v2 = __ldg(vp + lane);        // v[128:256] of original
    const float4 v3 = __ldg(vp + 32 + lane);   // v[256:384]

    // Streaming data: zero reuse -> evict-first (.cs).
    // All 11 loads are independent -> issue back-to-back (MLP=11/warp).
    const float4* ep  = reinterpret_cast<const float4*>(ent + (size_t)warp * D);
    const float4* nep = reinterpret_cast<const float4*>(ne + (size_t)warp * (K * D));
    const float4* nrp = reinterpret_cast<const float4*>(nr + (size_t)warp * (K * D));

    const float4 e4 = __ldcs(ep + lane);

    float4 nek[K];
    float  logit[K];
    #pragma unroll
    for (int k = 0; k < K; k++) {
        nek[k]          = __ldcs(nep + k * 32 + lane);
        const float4 r4 = __ldcs(nrp + k * 32 + lane);
        logit[k] = dot4(nek[k], v2) + dot4(r4, v3);
    }
    #pragma unroll
    for (int k = 0; k < K; k++)
        logit[k] = warp_sum(logit[k]);   // every lane has all K logits

    // Softmax over K=5 (fp32)
    float m = logit[0];
    #pragma unroll
    for (int k = 1; k < K; k++) m = fmaxf(m, logit[k]);
    float ex[K], sum = 0.0f;
    #pragma unroll
    for (int k = 0; k < K; k++) { ex[k] = __expf(logit[k] - m); sum += ex[k]; }
    const float inv = 1.0f / sum;

    // Weighted sum of neighbor entity embeddings
    float4 acc = make_float4(0.f, 0.f, 0.f, 0.f);
    #pragma unroll
    for (int k = 0; k < K; k++) {
        const float a = ex[k] * inv;
        acc.x = fmaf(a, nek[k].x, acc.x);
        acc.y = fmaf(a, nek[k].y, acc.y);
        acc.z = fmaf(a, nek[k].z, acc.z);
        acc.w = fmaf(a, nek[k].w, acc.w);
    }

    // Output: [e | neigh_att]; both stores deferred to the end
    float4* op = reinterpret_cast<float4*>(out + (size_t)warp * (2 * D));
    __stcs(op + lane, e4);
    __stcs(op + 32 + lane, acc);
}

extern "C" void kernel_launch(void* const* d_in, const int* in_sizes, int n_in,
                              void* d_out, int out_size) {
    const float* ent = (const float*)d_in[0];   // entity_embedding   [B,N,128]
    const float* ne  = (const float*)d_in[1];   // neigh_entity       [B,N,5,128]
    const float* nr  = (const float*)d_in[2];   // neigh_relation     [B,N,5,128]
    const float* W1  = (const float*)d_in[3];   // [384,128]
    const float* W2  = (const float*)d_in[5];   // [128,1]
    float* out = (float*)d_out;

    const int total_pairs = in_sizes[0] / D;    // B*N

    // 256 warps needed -> 32 blocks of 8 warps
    fold_mlp_kernel<<<32, THREADS>>>(W1, W2);

    const int blocks = (total_pairs + WARPS_PER_BLOCK - 1) / WARPS_PER_BLOCK;
    kgat_kernel<<<blocks, THREADS>>>(ent, ne, nr, out, total_pairs);
}